// round 16
// baseline (speedup 1.0000x reference)
#include <cuda_runtime.h>
#include <cuda_bf16.h>
#include <math.h>

#define BB 256
#define SS 512
#define EE 128
#define HH 256
#define NCOL 8
#define BT 32
#define HPAD 264
#define APAD 264

typedef unsigned int u32;

__device__ u32   g_epack[BB * SS * HH];     // packed bf16 hi|lo encoder states
__device__ u32   g_hpack[2][BB * HH];       // process-block h ping-pong (packed)
__device__ float g_hfin[BB * HH];
__device__ u32   g_wpack[HH * HH];          // packed Wref
__device__ float g_M[1024 * 2];
__device__ float g_bias[1024];
__device__ float g_xp[1024];
__device__ float g_xT[SS * 2 * BB];         // transposed inputs [step][c][b]
__device__ float g_q[BB * HH];
__device__ float g_u[BB * SS];
__device__ __align__(64) int g_flags[NCOL * 1024 * 16];

__device__ __forceinline__ float tanhap(float x) {
    float y; asm("tanh.approx.f32 %0,%1;" : "=f"(y) : "f"(x)); return y;
}
__device__ __forceinline__ float sigap(float x) {
    return fmaf(0.5f, tanhap(0.5f * x), 0.5f);
}
__device__ __forceinline__ u32 smem_u32(const void* p) {
    u32 a;
    asm("{ .reg .u64 t; cvta.to.shared.u64 t, %1; cvt.u32.u64 %0, t; }" : "=r"(a) : "l"(p));
    return a;
}
__device__ __forceinline__ void ldsm4(u32& r0, u32& r1, u32& r2, u32& r3, u32 addr) {
    asm volatile("ldmatrix.sync.aligned.m8n8.x4.shared.b16 {%0,%1,%2,%3},[%4];"
                 : "=r"(r0), "=r"(r1), "=r"(r2), "=r"(r3) : "r"(addr));
}
__device__ __forceinline__ void mma16816(float& c0, float& c1, float& c2, float& c3,
                                         u32 a0, u32 a1, u32 a2, u32 a3, u32 b0, u32 b1) {
    asm volatile("mma.sync.aligned.m16n8k16.row.col.f32.bf16.bf16.f32 "
                 "{%0,%1,%2,%3},{%4,%5,%6,%7},{%8,%9},{%0,%1,%2,%3};"
                 : "+f"(c0), "+f"(c1), "+f"(c2), "+f"(c3)
                 : "r"(a0), "r"(a1), "r"(a2), "r"(a3), "r"(b0), "r"(b1));
}
__device__ __forceinline__ u32 pack_hilo(float x, float y, bool lo) {
    __nv_bfloat16 xh = __float2bfloat16(x);
    __nv_bfloat16 yh = __float2bfloat16(y);
    if (lo) {
        xh = __float2bfloat16(x - __bfloat162float(xh));
        yh = __float2bfloat16(y - __bfloat162float(yh));
    }
    return (u32)__bfloat16_as_ushort(xh) | ((u32)__bfloat16_as_ushort(yh) << 16);
}
#define LDACQ4(r0, r1, r2, r3, p) \
    asm volatile("ld.acquire.gpu.global.v4.b32 {%0,%1,%2,%3},[%4];" \
                 : "=r"(r0), "=r"(r1), "=r"(r2), "=r"(r3) : "l"(p) : "memory")

__global__ void init_kernel(const float* __restrict__ encWih, const float* __restrict__ Wemb,
                            const float* __restrict__ encBih, const float* __restrict__ encBhh,
                            const float* __restrict__ pbWih,  const float* __restrict__ decIn,
                            const float* __restrict__ pbBih,  const float* __restrict__ pbBhh)
{
    int r = blockIdx.x * blockDim.x + threadIdx.x;
    if (r >= 1024) return;
    float m0 = 0.f, m1 = 0.f, xp = 0.f;
    for (int e = 0; e < EE; e++) {
        float w = encWih[r * EE + e];
        m0 = fmaf(w, Wemb[e * 2 + 0], m0);
        m1 = fmaf(w, Wemb[e * 2 + 1], m1);
        xp = fmaf(pbWih[r * EE + e], decIn[e], xp);
    }
    g_M[2 * r] = m0; g_M[2 * r + 1] = m1;
    g_bias[r] = encBih[r] + encBhh[r];
    g_xp[r]   = xp + pbBih[r] + pbBhh[r];
#pragma unroll
    for (int q = 0; q < 128; q++) g_flags[r * 128 + q] = 0;
}

__global__ void xpose_kernel(const float* __restrict__ inp)
{
    int b = blockIdx.x, t = threadIdx.x;          // t = step*2 + c
    float v = inp[(size_t)b * 1024 + t];
    g_xT[(size_t)(t >> 1) * 512 + (t & 1) * 256 + b] = v;
}

__global__ void pack_w_kernel(const float* __restrict__ Wref)
{
    int i = blockIdx.x * 256 + threadIdx.x;
    float v = Wref[i];
    __nv_bfloat16 h = __float2bfloat16(v);
    __nv_bfloat16 l = __float2bfloat16(v - __bfloat162float(h));
    g_wpack[i] = (u32)__bfloat16_as_ushort(h) | ((u32)__bfloat16_as_ushort(l) << 16);
}

// B frags, gate-interleaved: MMA col n -> weight row (n&3)*HH + j0 + (n>>2)
__device__ __forceinline__ void load_B(const float* __restrict__ W, int j0, int w, int lane,
                                       u32 (&bhi)[16][2], u32 (&blo)[16][2])
{
    int n = w * 8 + (lane >> 2);
    int grow = (n & 3) * HH + j0 + (n >> 2);
    const float* wr = W + (size_t)grow * HH;
    int kc = (lane & 3) * 2;
#pragma unroll
    for (int ks = 0; ks < 16; ks++) {
#pragma unroll
        for (int half = 0; half < 2; half++) {
            float2 v = __ldg((const float2*)(wr + ks * 16 + half * 8 + kc));
            bhi[ks][half] = pack_hilo(v.x, v.y, false);
            blo[ks][half] = pack_hilo(v.x, v.y, true);
        }
    }
}

__global__ void __launch_bounds__(256)
lstm_kernel(const float* __restrict__ encWhh, const float* __restrict__ pbWhh)
{
    __shared__ __align__(16) __nv_bfloat16 s_hi[32][HPAD];
    __shared__ __align__(16) __nv_bfloat16 s_lo[32][HPAD];

    const int tid  = threadIdx.x;
    const int lane = tid & 31;
    const int w    = tid >> 5;
    const int col  = blockIdx.x & 7;
    const int slc  = blockIdx.x >> 3;
    const int b0g  = col * BT;
    const int j0   = slc * 16;

    // zero h tiles (step 0 mma reads zeros)
#pragma unroll
    for (int i = 0; i < 8; i++) {
        int idx = tid + i * 256;
        int b = idx >> 6, ft = idx & 63;
        *(uint2*)&s_hi[b][4 * ft] = make_uint2(0u, 0u);
        *(uint2*)&s_lo[b][4 * ft] = make_uint2(0u, 0u);
    }

    u32 bhi[16][2], blo[16][2];
    load_B(encWhh, j0, w, lane, bhi, blo);

    const int jd = 2 * w + ((lane & 3) >> 1);
    const int rq = lane >> 2;
    const bool ifown = ((lane & 1) == 0);
    float cex[4], cey[4], ceb[4], cxp[4];
#pragma unroll
    for (int m = 0; m < 4; m++) {
        int grow = m * HH + j0 + jd;
        cex[m] = g_M[2 * grow]; cey[m] = g_M[2 * grow + 1];
        ceb[m] = g_bias[grow];  cxp[m] = g_xp[grow];
    }
    float cst[4] = {0.f, 0.f, 0.f, 0.f};

    const int arow = lane & 15;
    const int koff = (lane >> 4) * 8;
    u32 ah[2], al[2];
#pragma unroll
    for (int mt = 0; mt < 2; mt++) {
        ah[mt] = smem_u32(&s_hi[mt * 16 + arow][koff]);
        al[mt] = smem_u32(&s_lo[mt * 16 + arow][koff]);
    }
    __syncthreads();

    for (int step = 0; step < 1024; step++) {
        const bool enc = step < 512;
        if (step == 512) load_B(pbWhh, j0, w, lane, bhi, blo);

        if (step >= 1) {
            // all threads poll the 16 slice flags of step-1 (overlapped v4 acquires)
            const int* fb = g_flags + (size_t)((col << 10) + step - 1) * 16;
            for (;;) {
                int a0, a1, a2, a3, b0, b1, b2, b3;
                int c0, c1, c2, c3, d0, d1, d2, d3;
                LDACQ4(a0, a1, a2, a3, fb);
                LDACQ4(b0, b1, b2, b3, fb + 4);
                LDACQ4(c0, c1, c2, c3, fb + 8);
                LDACQ4(d0, d1, d2, d3, fb + 12);
                if ((a0 & a1 & a2 & a3 & b0 & b1 & b2 & b3 &
                     c0 & c1 & c2 & c3 & d0 & d1 & d2 & d3) != 0) break;
                __nanosleep(20);
            }
            // vectorized fill: 8x (LDG.128 + 4 PRMT + 2 STS.64) per thread
#pragma unroll
            for (int i = 0; i < 8; i++) {
                int idx = tid + i * 256;
                int b = idx >> 6, ft = idx & 63;
                const u32* src = (step <= 512)
                    ? (g_epack + ((size_t)(b0g + b) * SS + (step - 1)) * HH + 4 * ft)
                    : (g_hpack[(step - 1) & 1] + (size_t)(b0g + b) * HH + 4 * ft);
                uint4 U = __ldcg((const uint4*)src);
                u32 hi01 = __byte_perm(U.x, U.y, 0x5410);
                u32 hi23 = __byte_perm(U.z, U.w, 0x5410);
                u32 lo01 = __byte_perm(U.x, U.y, 0x7632);
                u32 lo23 = __byte_perm(U.z, U.w, 0x7632);
                *(uint2*)&s_hi[b][4 * ft] = make_uint2(hi01, hi23);
                *(uint2*)&s_lo[b][4 * ft] = make_uint2(lo01, lo23);
            }
        }
        __syncthreads();

        // coalesced x loads from transposed buffer
        float2 xv[4];
        if (enc) {
            const float* xr = g_xT + (size_t)step * 512;
#pragma unroll
            for (int q = 0; q < 4; q++) {
                int b = b0g + rq + q * 8;
                xv[q] = make_float2(__ldg(xr + b), __ldg(xr + 256 + b));
            }
        }

        float C0[4] = {0.f, 0.f, 0.f, 0.f};
        float C1[4] = {0.f, 0.f, 0.f, 0.f};
#pragma unroll
        for (int ks = 0; ks < 16; ks++) {
            u32 h0a, h0b, h0c, h0d, l0a, l0b, l0c, l0d;
            u32 h1a, h1b, h1c, h1d, l1a, l1b, l1c, l1d;
            ldsm4(h0a, h0b, h0c, h0d, ah[0] + ks * 32);
            ldsm4(l0a, l0b, l0c, l0d, al[0] + ks * 32);
            ldsm4(h1a, h1b, h1c, h1d, ah[1] + ks * 32);
            ldsm4(l1a, l1b, l1c, l1d, al[1] + ks * 32);
            mma16816(C0[0], C0[1], C0[2], C0[3], h0a, h0b, h0c, h0d, bhi[ks][0], bhi[ks][1]);
            mma16816(C0[0], C0[1], C0[2], C0[3], l0a, l0b, l0c, l0d, bhi[ks][0], bhi[ks][1]);
            mma16816(C0[0], C0[1], C0[2], C0[3], h0a, h0b, h0c, h0d, blo[ks][0], blo[ks][1]);
            mma16816(C1[0], C1[1], C1[2], C1[3], h1a, h1b, h1c, h1d, bhi[ks][0], bhi[ks][1]);
            mma16816(C1[0], C1[1], C1[2], C1[3], l1a, l1b, l1c, l1d, bhi[ks][0], bhi[ks][1]);
            mma16816(C1[0], C1[1], C1[2], C1[3], h1a, h1b, h1c, h1d, blo[ks][0], blo[ks][1]);
        }

        float own[8] = {C0[0], C0[1], C0[2], C0[3], C1[0], C1[1], C1[2], C1[3]};
        float par[8];
#pragma unroll
        for (int i = 0; i < 8; i++) par[i] = __shfl_xor_sync(0xffffffffu, own[i], 1);
#pragma unroll
        for (int q = 0; q < 4; q++) {
            float gi, gf, gg, go;
            if (ifown) { gi = own[2 * q]; gf = own[2 * q + 1]; gg = par[2 * q]; go = par[2 * q + 1]; }
            else       { gi = par[2 * q]; gf = par[2 * q + 1]; gg = own[2 * q]; go = own[2 * q + 1]; }
            if (enc) {
                float2 x = xv[q];
                gi += fmaf(cex[0], x.x, fmaf(cey[0], x.y, ceb[0]));
                gf += fmaf(cex[1], x.x, fmaf(cey[1], x.y, ceb[1]));
                gg += fmaf(cex[2], x.x, fmaf(cey[2], x.y, ceb[2]));
                go += fmaf(cex[3], x.x, fmaf(cey[3], x.y, ceb[3]));
            } else {
                gi += cxp[0]; gf += cxp[1]; gg += cxp[2]; go += cxp[3];
            }
            float c = cst[q];
            c = sigap(gf) * c + sigap(gi) * tanhap(gg);
            float h = sigap(go) * tanhap(c);
            cst[q] = c;
            if (ifown) {
                int b = b0g + rq + q * 8;
                __nv_bfloat16 hh = __float2bfloat16(h);
                u32 packed = (u32)__bfloat16_as_ushort(hh) |
                    ((u32)__bfloat16_as_ushort(__float2bfloat16(h - __bfloat162float(hh))) << 16);
                if (enc)
                    g_epack[((size_t)b * SS + step) * HH + j0 + jd] = packed;
                else
                    g_hpack[step & 1][(size_t)b * HH + j0 + jd] = packed;
                if (step == 1023) g_hfin[(size_t)b * HH + j0 + jd] = h;
            }
        }
        __syncthreads();
        if (tid == 0)
            asm volatile("st.release.gpu.global.b32 [%0], %1;"
                         :: "l"(&g_flags[(size_t)((col << 10) + step) * 16 + slc]), "r"(1)
                         : "memory");
    }
}

// q = h_final @ Wq^T + bq : 8 batches per block, 8-way ILP
__global__ void qproj_kernel(const float* __restrict__ Wq, const float* __restrict__ bq)
{
    __shared__ float hb[8][HH];
    int b0 = blockIdx.x * 8, jx = threadIdx.x;
#pragma unroll
    for (int i = 0; i < 8; i++) hb[i][jx] = g_hfin[(size_t)(b0 + i) * HH + jx];
    __syncthreads();
    float acc[8];
    float bv = bq[jx];
#pragma unroll
    for (int i = 0; i < 8; i++) acc[i] = bv;
    const float* wv = Wq + (size_t)jx * HH;
#pragma unroll 8
    for (int k = 0; k < HH; k++) {
        float wk = __ldg(wv + k);
#pragma unroll
        for (int i = 0; i < 8; i++) acc[i] = fmaf(hb[i][k], wk, acc[i]);
    }
#pragma unroll
    for (int i = 0; i < 8; i++) g_q[(size_t)(b0 + i) * HH + jx] = acc[i];
}

// attention u: tensor-core version (proven round-13 structure)
__global__ void __launch_bounds__(256)
attnU_kernel(const float* __restrict__ bref, const float* __restrict__ V)
{
    extern __shared__ __nv_bfloat16 smb[];
    __nv_bfloat16* e_hi = smb;
    __nv_bfloat16* e_lo = smb + 64 * APAD;
    __nv_bfloat16* w_hi = smb + 2 * 64 * APAD;
    __nv_bfloat16* w_lo = smb + 3 * 64 * APAD;
    float* sadd = (float*)(smb + 4 * 64 * APAD);
    float* sv   = sadd + 256;
    float* us   = sv + 256;

    const int tid = threadIdx.x, lane = tid & 31, w = tid >> 5;
    const int wm = w & 3, wn = w >> 2;
    const int b = blockIdx.y, s0 = blockIdx.x * 64;

    sadd[tid] = bref[tid] + g_q[(size_t)b * HH + tid];
    sv[tid]   = V[tid];

    const u32* ep = g_epack + ((size_t)b * SS + s0) * HH;
#pragma unroll
    for (int i = 0; i < 32; i++) {
        int idx = tid + i * 256;
        int s = idx >> 7, kp = idx & 127;
        uint2 u = __ldcg((const uint2*)(ep + (size_t)s * HH + 2 * kp));
        *(u32*)&e_hi[s * APAD + 2 * kp] = (u.x & 0xFFFFu) | (u.y << 16);
        *(u32*)&e_lo[s * APAD + 2 * kp] = (u.x >> 16) | (u.y & 0xFFFF0000u);
    }

    const int arow = lane & 15, koff = (lane >> 4) * 8;
    const u32 abase_h = smem_u32(&e_hi[(wm * 16 + arow) * APAD + koff]);
    const u32 abase_l = smem_u32(&e_lo[(wm * 16 + arow) * APAD + koff]);
    const int nb = wn * 32 + (lane >> 2);
    const int kc = (lane & 3) * 2;

    float u0 = 0.f, u1 = 0.f;
    for (int jt = 0; jt < 4; jt++) {
        __syncthreads();
        const u32* wp = g_wpack + (size_t)(jt * 64) * HH;
#pragma unroll
        for (int i = 0; i < 32; i++) {
            int idx = tid + i * 256;
            int j = idx >> 7, kp = idx & 127;
            uint2 u = __ldcg((const uint2*)(wp + (size_t)j * HH + 2 * kp));
            *(u32*)&w_hi[j * APAD + 2 * kp] = (u.x & 0xFFFFu) | (u.y << 16);
            *(u32*)&w_lo[j * APAD + 2 * kp] = (u.x >> 16) | (u.y & 0xFFFF0000u);
        }
        __syncthreads();

        float C[4][4];
#pragma unroll
        for (int nt = 0; nt < 4; nt++) { C[nt][0] = C[nt][1] = C[nt][2] = C[nt][3] = 0.f; }

#pragma unroll
        for (int ks = 0; ks < 16; ks++) {
            u32 a0, a1, a2, a3, l0, l1, l2, l3;
            ldsm4(a0, a1, a2, a3, abase_h + ks * 32);
            ldsm4(l0, l1, l2, l3, abase_l + ks * 32);
#pragma unroll
            for (int nt = 0; nt < 4; nt++) {
                const __nv_bfloat16* wr_h = &w_hi[(nb + nt * 8) * APAD + ks * 16 + kc];
                const __nv_bfloat16* wr_l = &w_lo[(nb + nt * 8) * APAD + ks * 16 + kc];
                u32 bh0 = *(const u32*)wr_h;
                u32 bh1 = *(const u32*)(wr_h + 8);
                u32 bl0 = *(const u32*)wr_l;
                u32 bl1 = *(const u32*)(wr_l + 8);
                mma16816(C[nt][0], C[nt][1], C[nt][2], C[nt][3], a0, a1, a2, a3, bh0, bh1);
                mma16816(C[nt][0], C[nt][1], C[nt][2], C[nt][3], l0, l1, l2, l3, bh0, bh1);
                mma16816(C[nt][0], C[nt][1], C[nt][2], C[nt][3], a0, a1, a2, a3, bl0, bl1);
            }
        }
#pragma unroll
        for (int nt = 0; nt < 4; nt++) {
            int j = jt * 64 + wn * 32 + nt * 8 + (lane & 3) * 2;
            float ad0 = sadd[j], ad1 = sadd[j + 1];
            float v0 = sv[j], v1 = sv[j + 1];
            u0 += tanhap(C[nt][0] + ad0) * v0 + tanhap(C[nt][1] + ad1) * v1;
            u1 += tanhap(C[nt][2] + ad0) * v0 + tanhap(C[nt][3] + ad1) * v1;
        }
    }
    u0 += __shfl_xor_sync(0xffffffffu, u0, 1);
    u0 += __shfl_xor_sync(0xffffffffu, u0, 2);
    u1 += __shfl_xor_sync(0xffffffffu, u1, 1);
    u1 += __shfl_xor_sync(0xffffffffu, u1, 2);
    if ((lane & 3) == 0) {
        us[wn * 64 + wm * 16 + (lane >> 2)]     = u0;
        us[wn * 64 + wm * 16 + 8 + (lane >> 2)] = u1;
    }
    __syncthreads();
    if (tid < 64)
        g_u[(size_t)b * SS + s0 + tid] = us[tid] + us[64 + tid];
}

__global__ void final_kernel(const float* __restrict__ Wd1, const float* __restrict__ Wd2,
                             float* __restrict__ out)
{
    __shared__ float al[SS];
    __shared__ float red[8];
    __shared__ float gb[HH];
    int b = blockIdx.x, tid = threadIdx.x;
    int lane = tid & 31, wid = tid >> 5;

    float u0 = g_u[(size_t)b * SS + tid];
    float u1 = g_u[(size_t)b * SS + 256 + tid];

    float m = fmaxf(u0, u1);
#pragma unroll
    for (int o = 16; o > 0; o >>= 1) m = fmaxf(m, __shfl_xor_sync(0xffffffffu, m, o));
    if (lane == 0) red[wid] = m;
    __syncthreads();
    float M2 = red[0];
#pragma unroll
    for (int w = 1; w < 8; w++) M2 = fmaxf(M2, red[w]);
    __syncthreads();

    float e0 = __expf(u0 - M2), e1 = __expf(u1 - M2);
    al[tid] = e0; al[tid + 256] = e1;
    float s = e0 + e1;
#pragma unroll
    for (int o = 16; o > 0; o >>= 1) s += __shfl_xor_sync(0xffffffffu, s, o);
    if (lane == 0) red[wid] = s;
    __syncthreads();
    float Ssum = 0.f;
#pragma unroll
    for (int w = 0; w < 8; w++) Ssum += red[w];
    __syncthreads();

    // glimpse from packed encoder states (exact fp32 = hi + lo)
    float a0 = 0.f, a1 = 0.f, a2 = 0.f, a3 = 0.f;
    const u32* epk = g_epack + (size_t)b * SS * HH + tid;
#pragma unroll 2
    for (int sIdx = 0; sIdx < SS; sIdx += 8) {
        u32 uu[8];
#pragma unroll
        for (int i = 0; i < 8; i++) uu[i] = __ldcg(epk + (size_t)(sIdx + i) * HH);
#pragma unroll
        for (int i = 0; i < 8; i += 4) {
            float h0 = __uint_as_float(uu[i] << 16)     + __uint_as_float(uu[i] & 0xFFFF0000u);
            float h1 = __uint_as_float(uu[i + 1] << 16) + __uint_as_float(uu[i + 1] & 0xFFFF0000u);
            float h2 = __uint_as_float(uu[i + 2] << 16) + __uint_as_float(uu[i + 2] & 0xFFFF0000u);
            float h3 = __uint_as_float(uu[i + 3] << 16) + __uint_as_float(uu[i + 3] & 0xFFFF0000u);
            a0 = fmaf(al[sIdx + i], h0, a0);
            a1 = fmaf(al[sIdx + i + 1], h1, a1);
            a2 = fmaf(al[sIdx + i + 2], h2, a2);
            a3 = fmaf(al[sIdx + i + 3], h3, a3);
        }
    }
    gb[tid] = ((a0 + a1) + (a2 + a3)) / Ssum;
    __syncthreads();

    float t = 0.f;
    const float* w1 = Wd1 + (size_t)tid * HH;
#pragma unroll 8
    for (int k = 0; k < HH; k++) t = fmaf(gb[k], w1[k], t);
    t = fmaxf(t, 0.f) * __ldg(Wd2 + tid);
#pragma unroll
    for (int o = 16; o > 0; o >>= 1) t += __shfl_xor_sync(0xffffffffu, t, o);
    if (lane == 0) red[wid] = t;
    __syncthreads();
    if (tid == 0) {
        float r = 0.f;
#pragma unroll
        for (int w = 0; w < 8; w++) r += red[w];
        out[b] = r;
    }
}

extern "C" void kernel_launch(void* const* d_in, const int* in_sizes, int n_in,
                              void* d_out, int out_size)
{
    const float* inp    = (const float*)d_in[0];
    const float* Wemb   = (const float*)d_in[1];
    const float* decIn  = (const float*)d_in[2];
    const float* encWih = (const float*)d_in[3];
    const float* encWhh = (const float*)d_in[4];
    const float* encBih = (const float*)d_in[5];
    const float* encBhh = (const float*)d_in[6];
    const float* pbWih  = (const float*)d_in[7];
    const float* pbWhh  = (const float*)d_in[8];
    const float* pbBih  = (const float*)d_in[9];
    const float* pbBhh  = (const float*)d_in[10];
    const float* Wq     = (const float*)d_in[11];
    const float* bq     = (const float*)d_in[12];
    const float* Wref   = (const float*)d_in[13];
    const float* bref   = (const float*)d_in[14];
    const float* V      = (const float*)d_in[15];
    const float* Wd1    = (const float*)d_in[16];
    const float* Wd2    = (const float*)d_in[17];

    const int ATTN_SMEM = 4 * 64 * APAD * 2 + (256 + 256 + 128) * 4;
    cudaFuncSetAttribute(attnU_kernel, cudaFuncAttributeMaxDynamicSharedMemorySize, ATTN_SMEM);

    init_kernel<<<4, 256>>>(encWih, Wemb, encBih, encBhh, pbWih, decIn, pbBih, pbBhh);
    xpose_kernel<<<256, 1024>>>(inp);
    pack_w_kernel<<<256, 256>>>(Wref);
    lstm_kernel<<<NCOL * 16, 256>>>(encWhh, pbWhh);
    qproj_kernel<<<32, 256>>>(Wq, bq);
    attnU_kernel<<<dim3(SS / 64, BB), 256, ATTN_SMEM>>>(bref, V);
    final_kernel<<<BB, 256>>>(Wd1, Wd2, (float*)d_out);
}

// round 17
// speedup vs baseline: 1.3854x; 1.3854x over previous
#include <cuda_runtime.h>
#include <cuda_bf16.h>
#include <math.h>

#define BB 256
#define SS 512
#define EE 128
#define HH 256
#define NCOL 8
#define BT 32
#define HPAD 264
#define APAD 264

typedef unsigned int u32;

__device__ float g_enc_out[BB * SS * HH];
__device__ u32   g_epack[BB * SS * HH];     // packed bf16 hi|lo encoder states
__device__ u32   g_hpack[2][BB * HH];
__device__ float g_hfin[BB * HH];
__device__ u32   g_wpack[HH * HH];          // packed Wref
__device__ float g_M[1024 * 2];
__device__ float g_bias[1024];
__device__ float g_xp[1024];
__device__ float g_xT[SS * 2 * BB];         // transposed inputs [step][c][b]
__device__ float g_q[BB * HH];
__device__ float g_u[BB * SS];
__device__ u32   g_cnt[NCOL * 1024];

__device__ __forceinline__ float tanhap(float x) {
    float y; asm("tanh.approx.f32 %0,%1;" : "=f"(y) : "f"(x)); return y;
}
__device__ __forceinline__ float sigap(float x) {
    return fmaf(0.5f, tanhap(0.5f * x), 0.5f);
}
__device__ __forceinline__ u32 smem_u32(const void* p) {
    u32 a;
    asm("{ .reg .u64 t; cvta.to.shared.u64 t, %1; cvt.u32.u64 %0, t; }" : "=r"(a) : "l"(p));
    return a;
}
__device__ __forceinline__ void ldsm4(u32& r0, u32& r1, u32& r2, u32& r3, u32 addr) {
    asm volatile("ldmatrix.sync.aligned.m8n8.x4.shared.b16 {%0,%1,%2,%3},[%4];"
                 : "=r"(r0), "=r"(r1), "=r"(r2), "=r"(r3) : "r"(addr));
}
__device__ __forceinline__ void mma16816(float& c0, float& c1, float& c2, float& c3,
                                         u32 a0, u32 a1, u32 a2, u32 a3, u32 b0, u32 b1) {
    asm volatile("mma.sync.aligned.m16n8k16.row.col.f32.bf16.bf16.f32 "
                 "{%0,%1,%2,%3},{%4,%5,%6,%7},{%8,%9},{%0,%1,%2,%3};"
                 : "+f"(c0), "+f"(c1), "+f"(c2), "+f"(c3)
                 : "r"(a0), "r"(a1), "r"(a2), "r"(a3), "r"(b0), "r"(b1));
}
__device__ __forceinline__ u32 pack_hilo(float x, float y, bool lo) {
    __nv_bfloat16 xh = __float2bfloat16(x);
    __nv_bfloat16 yh = __float2bfloat16(y);
    if (lo) {
        xh = __float2bfloat16(x - __bfloat162float(xh));
        yh = __float2bfloat16(y - __bfloat162float(yh));
    }
    return (u32)__bfloat16_as_ushort(xh) | ((u32)__bfloat16_as_ushort(yh) << 16);
}

__global__ void init_kernel(const float* __restrict__ encWih, const float* __restrict__ Wemb,
                            const float* __restrict__ encBih, const float* __restrict__ encBhh,
                            const float* __restrict__ pbWih,  const float* __restrict__ decIn,
                            const float* __restrict__ pbBih,  const float* __restrict__ pbBhh)
{
    int r = blockIdx.x * blockDim.x + threadIdx.x;
    if (r >= 1024) return;
    float m0 = 0.f, m1 = 0.f, xp = 0.f;
    for (int e = 0; e < EE; e++) {
        float w = encWih[r * EE + e];
        m0 = fmaf(w, Wemb[e * 2 + 0], m0);
        m1 = fmaf(w, Wemb[e * 2 + 1], m1);
        xp = fmaf(pbWih[r * EE + e], decIn[e], xp);
    }
    g_M[2 * r] = m0; g_M[2 * r + 1] = m1;
    g_bias[r] = encBih[r] + encBhh[r];
    g_xp[r]   = xp + pbBih[r] + pbBhh[r];
#pragma unroll
    for (int q = 0; q < 8; q++) g_cnt[r * 8 + q] = 0;
}

__global__ void xpose_kernel(const float* __restrict__ inp)
{
    int b = blockIdx.x, t = threadIdx.x;          // t = step*2 + c
    float v = inp[(size_t)b * 1024 + t];
    g_xT[(size_t)(t >> 1) * 512 + (t & 1) * 256 + b] = v;
}

__global__ void pack_w_kernel(const float* __restrict__ Wref)
{
    int i = blockIdx.x * 256 + threadIdx.x;
    float v = Wref[i];
    __nv_bfloat16 h = __float2bfloat16(v);
    __nv_bfloat16 l = __float2bfloat16(v - __bfloat162float(h));
    g_wpack[i] = (u32)__bfloat16_as_ushort(h) | ((u32)__bfloat16_as_ushort(l) << 16);
}

// B frags, gate-interleaved: MMA col n -> weight row (n&3)*HH + j0 + (n>>2)
__device__ __forceinline__ void load_B(const float* __restrict__ W, int j0, int w, int lane,
                                       u32 (&bhi)[16][2], u32 (&blo)[16][2])
{
    int n = w * 8 + (lane >> 2);
    int grow = (n & 3) * HH + j0 + (n >> 2);
    const float* wr = W + (size_t)grow * HH;
    int kc = (lane & 3) * 2;
#pragma unroll
    for (int ks = 0; ks < 16; ks++) {
#pragma unroll
        for (int half = 0; half < 2; half++) {
            float2 v = __ldg((const float2*)(wr + ks * 16 + half * 8 + kc));
            bhi[ks][half] = pack_hilo(v.x, v.y, false);
            blo[ks][half] = pack_hilo(v.x, v.y, true);
        }
    }
}

__global__ void __launch_bounds__(256)
lstm_kernel(const float* __restrict__ encWhh, const float* __restrict__ pbWhh)
{
    __shared__ __align__(16) __nv_bfloat16 s_hi[32][HPAD];
    __shared__ __align__(16) __nv_bfloat16 s_lo[32][HPAD];

    const int tid  = threadIdx.x;
    const int lane = tid & 31;
    const int w    = tid >> 5;
    const int col  = blockIdx.x & 7;
    const int slc  = blockIdx.x >> 3;
    const int b0g  = col * BT;
    const int j0   = slc * 16;

#pragma unroll
    for (int i = 0; i < 16; i++) {
        int idx = tid + i * 256;
        int b = idx >> 7, kp = idx & 127;
        *(u32*)&s_hi[b][2 * kp] = 0u;
        *(u32*)&s_lo[b][2 * kp] = 0u;
    }

    u32 bhi[16][2], blo[16][2];
    load_B(encWhh, j0, w, lane, bhi, blo);

    const int jd = 2 * w + ((lane & 3) >> 1);
    const int rq = lane >> 2;
    const bool ifown = ((lane & 1) == 0);
    float cex[4], cey[4], ceb[4], cxp[4];
#pragma unroll
    for (int m = 0; m < 4; m++) {
        int grow = m * HH + j0 + jd;
        cex[m] = g_M[2 * grow]; cey[m] = g_M[2 * grow + 1];
        ceb[m] = g_bias[grow];  cxp[m] = g_xp[grow];
    }
    float cst[4] = {0.f, 0.f, 0.f, 0.f};

    const int arow = lane & 15;
    const int koff = (lane >> 4) * 8;
    u32 ah[2], al[2];
#pragma unroll
    for (int mt = 0; mt < 2; mt++) {
        ah[mt] = smem_u32(&s_hi[mt * 16 + arow][koff]);
        al[mt] = smem_u32(&s_lo[mt * 16 + arow][koff]);
    }
    __syncthreads();

    for (int step = 0; step < 1024; step++) {
        const bool enc = step < 512;
        if (step == 512) load_B(pbWhh, j0, w, lane, bhi, blo);

        if (step >= 1) {
            const u32* cp = &g_cnt[(col << 10) + step - 1];
            u32 v;
            for (;;) {
                asm volatile("ld.acquire.gpu.global.u32 %0,[%1];" : "=r"(v) : "l"(cp) : "memory");
                if (v >= 16u) break;
                __nanosleep(20);
            }
            const u32* hp = (step <= 512) ? nullptr : g_hpack[(step - 1) & 1];
#pragma unroll
            for (int i = 0; i < 16; i++) {
                int idx = tid + i * 256;
                int b = idx >> 7, kp = idx & 127;
                const u32* src = (step <= 512)
                    ? (g_epack + ((size_t)(b0g + b) * SS + (step - 1)) * HH + 2 * kp)
                    : (hp + (size_t)(b0g + b) * HH + 2 * kp);
                uint2 u = __ldcg((const uint2*)src);
                *(u32*)&s_hi[b][2 * kp] = (u.x & 0xFFFFu) | (u.y << 16);
                *(u32*)&s_lo[b][2 * kp] = (u.x >> 16) | (u.y & 0xFFFF0000u);
            }
        }
        __syncthreads();

        float2 xv[4];
        if (enc) {
            const float* xr = g_xT + (size_t)step * 512;
#pragma unroll
            for (int q = 0; q < 4; q++) {
                int b = b0g + rq + q * 8;
                xv[q] = make_float2(__ldg(xr + b), __ldg(xr + 256 + b));
            }
        }

        float C0[4] = {0.f, 0.f, 0.f, 0.f};
        float C1[4] = {0.f, 0.f, 0.f, 0.f};
#pragma unroll
        for (int ks = 0; ks < 16; ks++) {
            u32 h0a, h0b, h0c, h0d, l0a, l0b, l0c, l0d;
            u32 h1a, h1b, h1c, h1d, l1a, l1b, l1c, l1d;
            ldsm4(h0a, h0b, h0c, h0d, ah[0] + ks * 32);
            ldsm4(l0a, l0b, l0c, l0d, al[0] + ks * 32);
            ldsm4(h1a, h1b, h1c, h1d, ah[1] + ks * 32);
            ldsm4(l1a, l1b, l1c, l1d, al[1] + ks * 32);
            mma16816(C0[0], C0[1], C0[2], C0[3], h0a, h0b, h0c, h0d, bhi[ks][0], bhi[ks][1]);
            mma16816(C0[0], C0[1], C0[2], C0[3], l0a, l0b, l0c, l0d, bhi[ks][0], bhi[ks][1]);
            mma16816(C0[0], C0[1], C0[2], C0[3], h0a, h0b, h0c, h0d, blo[ks][0], blo[ks][1]);
            mma16816(C1[0], C1[1], C1[2], C1[3], h1a, h1b, h1c, h1d, bhi[ks][0], bhi[ks][1]);
            mma16816(C1[0], C1[1], C1[2], C1[3], l1a, l1b, l1c, l1d, bhi[ks][0], bhi[ks][1]);
            mma16816(C1[0], C1[1], C1[2], C1[3], h1a, h1b, h1c, h1d, blo[ks][0], blo[ks][1]);
        }

        float own[8] = {C0[0], C0[1], C0[2], C0[3], C1[0], C1[1], C1[2], C1[3]};
        float par[8];
#pragma unroll
        for (int i = 0; i < 8; i++) par[i] = __shfl_xor_sync(0xffffffffu, own[i], 1);
#pragma unroll
        for (int q = 0; q < 4; q++) {
            float gi, gf, gg, go;
            if (ifown) { gi = own[2 * q]; gf = own[2 * q + 1]; gg = par[2 * q]; go = par[2 * q + 1]; }
            else       { gi = par[2 * q]; gf = par[2 * q + 1]; gg = own[2 * q]; go = own[2 * q + 1]; }
            if (enc) {
                float2 x = xv[q];
                gi += fmaf(cex[0], x.x, fmaf(cey[0], x.y, ceb[0]));
                gf += fmaf(cex[1], x.x, fmaf(cey[1], x.y, ceb[1]));
                gg += fmaf(cex[2], x.x, fmaf(cey[2], x.y, ceb[2]));
                go += fmaf(cex[3], x.x, fmaf(cey[3], x.y, ceb[3]));
            } else {
                gi += cxp[0]; gf += cxp[1]; gg += cxp[2]; go += cxp[3];
            }
            float c = cst[q];
            c = sigap(gf) * c + sigap(gi) * tanhap(gg);
            float h = sigap(go) * tanhap(c);
            cst[q] = c;
            if (ifown) {
                int b = b0g + rq + q * 8;
                __nv_bfloat16 hh = __float2bfloat16(h);
                u32 packed = (u32)__bfloat16_as_ushort(hh) |
                    ((u32)__bfloat16_as_ushort(__float2bfloat16(h - __bfloat162float(hh))) << 16);
                if (enc) {
                    g_enc_out[((size_t)b * SS + step) * HH + j0 + jd] = h;
                    g_epack[((size_t)b * SS + step) * HH + j0 + jd] = packed;
                }
                if (step == 1023) g_hfin[(size_t)b * HH + j0 + jd] = h;
                g_hpack[step & 1][(size_t)b * HH + j0 + jd] = packed;
            }
        }
        __syncthreads();
        if (tid == 0)
            asm volatile("red.release.gpu.global.add.u32 [%0], %1;"
                         :: "l"(&g_cnt[(col << 10) + step]), "r"(1u) : "memory");
    }
}

// q = h_final @ Wq^T + bq : 8 batches per block, 8-way ILP
__global__ void qproj_kernel(const float* __restrict__ Wq, const float* __restrict__ bq)
{
    __shared__ float hb[8][HH];
    int b0 = blockIdx.x * 8, jx = threadIdx.x;
#pragma unroll
    for (int i = 0; i < 8; i++) hb[i][jx] = g_hfin[(size_t)(b0 + i) * HH + jx];
    __syncthreads();
    float acc[8];
    float bv = bq[jx];
#pragma unroll
    for (int i = 0; i < 8; i++) acc[i] = bv;
    const float* wv = Wq + (size_t)jx * HH;
#pragma unroll 8
    for (int k = 0; k < HH; k++) {
        float wk = __ldg(wv + k);
#pragma unroll
        for (int i = 0; i < 8; i++) acc[i] = fmaf(hb[i][k], wk, acc[i]);
    }
#pragma unroll
    for (int i = 0; i < 8; i++) g_q[(size_t)(b0 + i) * HH + jx] = acc[i];
}

// attention u: tensor-core version (round-13 structure, tanh.approx epilogue)
__global__ void __launch_bounds__(256)
attnU_kernel(const float* __restrict__ bref, const float* __restrict__ V)
{
    extern __shared__ __nv_bfloat16 smb[];
    __nv_bfloat16* e_hi = smb;
    __nv_bfloat16* e_lo = smb + 64 * APAD;
    __nv_bfloat16* w_hi = smb + 2 * 64 * APAD;
    __nv_bfloat16* w_lo = smb + 3 * 64 * APAD;
    float* sadd = (float*)(smb + 4 * 64 * APAD);
    float* sv   = sadd + 256;
    float* us   = sv + 256;

    const int tid = threadIdx.x, lane = tid & 31, w = tid >> 5;
    const int wm = w & 3, wn = w >> 2;
    const int b = blockIdx.y, s0 = blockIdx.x * 64;

    sadd[tid] = bref[tid] + g_q[(size_t)b * HH + tid];
    sv[tid]   = V[tid];

    const u32* ep = g_epack + ((size_t)b * SS + s0) * HH;
#pragma unroll
    for (int i = 0; i < 32; i++) {
        int idx = tid + i * 256;
        int s = idx >> 7, kp = idx & 127;
        uint2 u = __ldcg((const uint2*)(ep + (size_t)s * HH + 2 * kp));
        *(u32*)&e_hi[s * APAD + 2 * kp] = (u.x & 0xFFFFu) | (u.y << 16);
        *(u32*)&e_lo[s * APAD + 2 * kp] = (u.x >> 16) | (u.y & 0xFFFF0000u);
    }

    const int arow = lane & 15, koff = (lane >> 4) * 8;
    const u32 abase_h = smem_u32(&e_hi[(wm * 16 + arow) * APAD + koff]);
    const u32 abase_l = smem_u32(&e_lo[(wm * 16 + arow) * APAD + koff]);
    const int nb = wn * 32 + (lane >> 2);
    const int kc = (lane & 3) * 2;

    float u0 = 0.f, u1 = 0.f;
    for (int jt = 0; jt < 4; jt++) {
        __syncthreads();
        const u32* wp = g_wpack + (size_t)(jt * 64) * HH;
#pragma unroll
        for (int i = 0; i < 32; i++) {
            int idx = tid + i * 256;
            int j = idx >> 7, kp = idx & 127;
            uint2 u = __ldcg((const uint2*)(wp + (size_t)j * HH + 2 * kp));
            *(u32*)&w_hi[j * APAD + 2 * kp] = (u.x & 0xFFFFu) | (u.y << 16);
            *(u32*)&w_lo[j * APAD + 2 * kp] = (u.x >> 16) | (u.y & 0xFFFF0000u);
        }
        __syncthreads();

        float C[4][4];
#pragma unroll
        for (int nt = 0; nt < 4; nt++) { C[nt][0] = C[nt][1] = C[nt][2] = C[nt][3] = 0.f; }

#pragma unroll
        for (int ks = 0; ks < 16; ks++) {
            u32 a0, a1, a2, a3, l0, l1, l2, l3;
            ldsm4(a0, a1, a2, a3, abase_h + ks * 32);
            ldsm4(l0, l1, l2, l3, abase_l + ks * 32);
#pragma unroll
            for (int nt = 0; nt < 4; nt++) {
                const __nv_bfloat16* wr_h = &w_hi[(nb + nt * 8) * APAD + ks * 16 + kc];
                const __nv_bfloat16* wr_l = &w_lo[(nb + nt * 8) * APAD + ks * 16 + kc];
                u32 bh0 = *(const u32*)wr_h;
                u32 bh1 = *(const u32*)(wr_h + 8);
                u32 bl0 = *(const u32*)wr_l;
                u32 bl1 = *(const u32*)(wr_l + 8);
                mma16816(C[nt][0], C[nt][1], C[nt][2], C[nt][3], a0, a1, a2, a3, bh0, bh1);
                mma16816(C[nt][0], C[nt][1], C[nt][2], C[nt][3], l0, l1, l2, l3, bh0, bh1);
                mma16816(C[nt][0], C[nt][1], C[nt][2], C[nt][3], a0, a1, a2, a3, bl0, bl1);
            }
        }
#pragma unroll
        for (int nt = 0; nt < 4; nt++) {
            int j = jt * 64 + wn * 32 + nt * 8 + (lane & 3) * 2;
            float ad0 = sadd[j], ad1 = sadd[j + 1];
            float v0 = sv[j], v1 = sv[j + 1];
            u0 += tanhap(C[nt][0] + ad0) * v0 + tanhap(C[nt][1] + ad1) * v1;
            u1 += tanhap(C[nt][2] + ad0) * v0 + tanhap(C[nt][3] + ad1) * v1;
        }
    }
    u0 += __shfl_xor_sync(0xffffffffu, u0, 1);
    u0 += __shfl_xor_sync(0xffffffffu, u0, 2);
    u1 += __shfl_xor_sync(0xffffffffu, u1, 1);
    u1 += __shfl_xor_sync(0xffffffffu, u1, 2);
    if ((lane & 3) == 0) {
        us[wn * 64 + wm * 16 + (lane >> 2)]     = u0;
        us[wn * 64 + wm * 16 + 8 + (lane >> 2)] = u1;
    }
    __syncthreads();
    if (tid < 64)
        g_u[(size_t)b * SS + s0 + tid] = us[tid] + us[64 + tid];
}

__global__ void final_kernel(const float* __restrict__ Wd1, const float* __restrict__ Wd2,
                             float* __restrict__ out)
{
    __shared__ float al[SS];
    __shared__ float red[8];
    __shared__ float gb[HH];
    int b = blockIdx.x, tid = threadIdx.x;
    int lane = tid & 31, wid = tid >> 5;

    float u0 = g_u[(size_t)b * SS + tid];
    float u1 = g_u[(size_t)b * SS + 256 + tid];

    float m = fmaxf(u0, u1);
#pragma unroll
    for (int o = 16; o > 0; o >>= 1) m = fmaxf(m, __shfl_xor_sync(0xffffffffu, m, o));
    if (lane == 0) red[wid] = m;
    __syncthreads();
    float M2 = red[0];
#pragma unroll
    for (int w = 1; w < 8; w++) M2 = fmaxf(M2, red[w]);
    __syncthreads();

    float e0 = __expf(u0 - M2), e1 = __expf(u1 - M2);
    al[tid] = e0; al[tid + 256] = e1;
    float s = e0 + e1;
#pragma unroll
    for (int o = 16; o > 0; o >>= 1) s += __shfl_xor_sync(0xffffffffu, s, o);
    if (lane == 0) red[wid] = s;
    __syncthreads();
    float Ssum = 0.f;
#pragma unroll
    for (int w = 0; w < 8; w++) Ssum += red[w];
    __syncthreads();

    float a0 = 0.f, a1 = 0.f, a2 = 0.f, a3 = 0.f;
    const float* ep = g_enc_out + (size_t)b * SS * HH + tid;
    for (int sIdx = 0; sIdx < SS; sIdx += 4) {
        a0 = fmaf(al[sIdx + 0], __ldcg(ep + (size_t)(sIdx + 0) * HH), a0);
        a1 = fmaf(al[sIdx + 1], __ldcg(ep + (size_t)(sIdx + 1) * HH), a1);
        a2 = fmaf(al[sIdx + 2], __ldcg(ep + (size_t)(sIdx + 2) * HH), a2);
        a3 = fmaf(al[sIdx + 3], __ldcg(ep + (size_t)(sIdx + 3) * HH), a3);
    }
    gb[tid] = ((a0 + a1) + (a2 + a3)) / Ssum;
    __syncthreads();

    float t = 0.f;
    const float* w1 = Wd1 + (size_t)tid * HH;
#pragma unroll 8
    for (int k = 0; k < HH; k++) t = fmaf(gb[k], w1[k], t);
    t = fmaxf(t, 0.f) * __ldg(Wd2 + tid);
#pragma unroll
    for (int o = 16; o > 0; o >>= 1) t += __shfl_xor_sync(0xffffffffu, t, o);
    if (lane == 0) red[wid] = t;
    __syncthreads();
    if (tid == 0) {
        float r = 0.f;
#pragma unroll
        for (int w = 0; w < 8; w++) r += red[w];
        out[b] = r;
    }
}

extern "C" void kernel_launch(void* const* d_in, const int* in_sizes, int n_in,
                              void* d_out, int out_size)
{
    const float* inp    = (const float*)d_in[0];
    const float* Wemb   = (const float*)d_in[1];
    const float* decIn  = (const float*)d_in[2];
    const float* encWih = (const float*)d_in[3];
    const float* encWhh = (const float*)d_in[4];
    const float* encBih = (const float*)d_in[5];
    const float* encBhh = (const float*)d_in[6];
    const float* pbWih  = (const float*)d_in[7];
    const float* pbWhh  = (const float*)d_in[8];
    const float* pbBih  = (const float*)d_in[9];
    const float* pbBhh  = (const float*)d_in[10];
    const float* Wq     = (const float*)d_in[11];
    const float* bq     = (const float*)d_in[12];
    const float* Wref   = (const float*)d_in[13];
    const float* bref   = (const float*)d_in[14];
    const float* V      = (const float*)d_in[15];
    const float* Wd1    = (const float*)d_in[16];
    const float* Wd2    = (const float*)d_in[17];

    const int ATTN_SMEM = 4 * 64 * APAD * 2 + (256 + 256 + 128) * 4;
    cudaFuncSetAttribute(attnU_kernel, cudaFuncAttributeMaxDynamicSharedMemorySize, ATTN_SMEM);

    init_kernel<<<4, 256>>>(encWih, Wemb, encBih, encBhh, pbWih, decIn, pbBih, pbBhh);
    xpose_kernel<<<256, 1024>>>(inp);
    pack_w_kernel<<<256, 256>>>(Wref);
    lstm_kernel<<<NCOL * 16, 256>>>(encWhh, pbWhh);
    qproj_kernel<<<32, 256>>>(Wq, bq);
    attnU_kernel<<<dim3(SS / 64, BB), 256, ATTN_SMEM>>>(bref, V);
    final_kernel<<<BB, 256>>>(Wd1, Wd2, (float*)d_out);
}